// round 13
// baseline (speedup 1.0000x reference)
#include <cuda_runtime.h>
#include <cuda_fp16.h>
#include <math.h>
#include <stdint.h>

#define BB   32
#define CC   256
#define HCH  14
#define PP   196
#define KCODES 8192
#define COLS 6272
#define BOW_ELEMS (BB*KCODES)
#define CODES_OFF BOW_ELEMS

#define KC 64                  // fp16 per chunk row = 128B (SW128)
#define NCHUNK 8               // 4 single-B (e1*f0) + 4 dual-B (e0*{f1,f0})
#define MT 128                 // M rows per CTA
#define NTT 128                // N cols per CTA
#define TILE_B 16384           // one 128x128B tile
#define STAGE (3*TILE_B)       // A + B0 + B1
#define NSTAGE 2
#define DSMEM (NSTAGE*STAGE + 1024)
#define KSEG (KCODES/MT)       // 64

// ---------------- scratch ----------------
__device__ __half g_e0[KCODES*CC], g_e1[KCODES*CC];
__device__ __half g_f0[COLS*CC],   g_f1[COLS*CC];
__device__ float g_esq[KCODES];
__device__ float g_fsq[COLS];
__device__ float g_pm[KSEG*COLS];
__device__ float g_ps[KSEG*COLS];
__device__ float g_colm[COLS];
__device__ float g_colr[COLS];

// ---------------- helpers ----------------
__device__ __forceinline__ uint32_t s2u(const void* p) {
    uint32_t a;
    asm("{ .reg .u64 t; cvta.to.shared.u64 t, %1; cvt.u32.u64 %0, t; }" : "=r"(a) : "l"(p));
    return a;
}
#define SWZ(o) ((o) ^ (((o) >> 3) & 0x70))
__device__ __forceinline__ void cp16(uint32_t dst, const void* src) {
    asm volatile("cp.async.cg.shared.global [%0], [%1], 16;" :: "r"(dst), "l"(src));
}
__device__ __forceinline__ void ldsm4(uint32_t* r, uint32_t addr) {
    asm volatile("ldmatrix.sync.aligned.m8n8.x4.shared.b16 {%0,%1,%2,%3}, [%4];"
                 : "=r"(r[0]), "=r"(r[1]), "=r"(r[2]), "=r"(r[3]) : "r"(addr));
}
__device__ __forceinline__ void mma16816(float* c, const uint32_t* a, const uint32_t* b) {
    asm volatile(
        "mma.sync.aligned.m16n8k16.row.col.f32.f16.f16.f32 "
        "{%0,%1,%2,%3}, {%4,%5,%6,%7}, {%8,%9}, {%0,%1,%2,%3};"
        : "+f"(c[0]), "+f"(c[1]), "+f"(c[2]), "+f"(c[3])
        : "r"(a[0]), "r"(a[1]), "r"(a[2]), "r"(a[3]), "r"(b[0]), "r"(b[1]));
}

// ---------------- prep: embedding fp16 hi/lo split + e_sq (warp per row) ----
__global__ void k_prep_emb(const float* __restrict__ emb) {
    int warp = (blockIdx.x * blockDim.x + threadIdx.x) >> 5;
    int lane = threadIdx.x & 31;
    if (warp >= KCODES) return;
    const float* r = emb + (size_t)warp * CC;
    double s = 0.0;
    #pragma unroll
    for (int i = 0; i < CC / 32; i++) {
        int c = lane + i * 32;
        float v = r[c];
        s += (double)v * (double)v;
        __half h = __float2half_rn(v);
        float r1 = v - __half2float(h);
        size_t o = (size_t)warp * CC + c;
        g_e0[o] = h; g_e1[o] = __float2half_rn(r1);
    }
    #pragma unroll
    for (int o = 16; o; o >>= 1) s += __shfl_xor_sync(0xFFFFFFFFu, s, o);
    if (lane == 0) g_esq[warp] = (float)s;
}

// crop + transpose features -> [col][c] fp16 hi/lo split
__global__ void k_prep_f(const float* __restrict__ feat) {
    __shared__ float tile[32][33];
    int tx = threadIdx.x, ty = threadIdx.y;
    int col = blockIdx.x * 32 + tx;
    int c   = blockIdx.y * 32 + ty;
    int b = col / PP, p = col - b * PP;
    int y = p / HCH + 1, x = p - (y - 1) * HCH + 1;
    tile[ty][tx] = feat[((size_t)(b * CC + c) * 16 + y) * 16 + x];
    __syncthreads();
    int colw = blockIdx.x * 32 + ty;
    int cw   = blockIdx.y * 32 + tx;
    float v = tile[tx][ty];
    __half h = __float2half_rn(v);
    float r1 = v - __half2float(h);
    size_t o = (size_t)colw * CC + cw;
    g_f0[o] = h; g_f1[o] = __float2half_rn(r1);
}

// f_sq: block per batch, thread = pixel, 4 fp64 accumulators for MLP
__global__ void k_fsq(const float* __restrict__ feat) {
    int b = blockIdx.x, t = threadIdx.x;          // t = y*16+x
    const float* fp = feat + (size_t)b * CC * 256 + t;
    double s0 = 0.0, s1 = 0.0, s2 = 0.0, s3 = 0.0;
    #pragma unroll 16
    for (int c = 0; c < CC; c += 4) {
        float v0 = fp[(size_t)(c + 0) * 256];
        float v1 = fp[(size_t)(c + 1) * 256];
        float v2 = fp[(size_t)(c + 2) * 256];
        float v3 = fp[(size_t)(c + 3) * 256];
        s0 += (double)v0 * v0; s1 += (double)v1 * v1;
        s2 += (double)v2 * v2; s3 += (double)v3 * v3;
    }
    double s = (s0 + s1) + (s2 + s3);
    int y = t >> 4, x = t & 15;
    if (y >= 1 && y <= 14 && x >= 1 && x <= 14)
        g_fsq[b * PP + (y - 1) * HCH + (x - 1)] = (float)s;
}

// ---------------------------------------------------------------------------
// Warp-MMA GEMM: CTA 128x128, 8 warps, warp tile 64x32, 2 CTAs/SM.
// fp16x2 emulation via 8 super-chunks:
//   ch 0-3: A=e1, B0=f0 (single-B, 64 MMA)
//   ch 4-7: A=e0, B0=f1, B1=f0 (dual-B: A fragments reused, 128 MMA)
// Double-buffered cp.async; epilogue: float2 streaming logits + partials.
// ---------------------------------------------------------------------------
__global__ __launch_bounds__(256, 2) void k_mma(float* __restrict__ out) {
    extern __shared__ char dsm[];
    __shared__ float     s_fsq[NTT];
    __shared__ float     s_esq[MT];
    __shared__ long long s_cbase[NTT];
    __shared__ float     s_rm[2][NTT];
    __shared__ float     s_rs[2][NTT];

    int tid = threadIdx.x, lane = tid & 31, wid = tid >> 5;
    int warp_m = wid >> 2, warp_n = wid & 3;     // warp tile: 64 m x 32 n
    int col0 = blockIdx.x * NTT, krow0 = blockIdx.y * MT;
    float* codes = out + CODES_OFF;
    uint32_t base = (s2u(dsm) + 1023u) & ~1023u;

    if (tid < NTT) {
        int col = col0 + tid;
        s_fsq[tid] = g_fsq[col];
        int b = col / PP, p = col - b * PP;
        s_cbase[tid] = (long long)b * KCODES * PP + p;
    }
    if (tid < MT) s_esq[tid] = g_esq[krow0 + tid];

    float acc[4][4][4];                          // [mi][ni][quad]
    #pragma unroll
    for (int mi = 0; mi < 4; mi++)
        #pragma unroll
        for (int ni = 0; ni < 4; ni++)
            #pragma unroll
            for (int q = 0; q < 4; q++) acc[mi][ni][q] = 0.0f;

    int rA = lane & 15, csA = lane >> 4;
    int rB = ((lane >> 4) << 3) + (lane & 7), csB = (lane >> 3) & 1;

    // hoisted per-thread smem read offsets (relative to tile base)
    uint32_t aoff[4], boff[2];
    #pragma unroll
    for (int mi = 0; mi < 4; mi++)
        aoff[mi] = SWZ((uint32_t)((warp_m * 64 + mi * 16 + rA) * 128 + csA * 16));
    boff[0] = SWZ((uint32_t)((warp_n * 32 + rB) * 128 + csB * 16));
    boff[1] = SWZ((uint32_t)((warp_n * 32 + 16 + rB) * 128 + csB * 16));

    // hoisted per-thread load addressing (invariant across chunks)
    uint32_t dstoff[4];
    size_t   srcoff[4];
    #pragma unroll
    for (int i = 0; i < 4; i++) {
        int u = tid + i * 256, r = u >> 3, g = u & 7;
        dstoff[i] = SWZ((uint32_t)(r * 128 + g * 16));
        srcoff[i] = (size_t)r * CC + g * 8;
    }

    auto issue = [&](int ch, int buf) {
        int c0 = (ch & 3) * KC;
        bool dual = (ch >= 4);
        const __half* pa  = (dual ? g_e0 : g_e1) + (size_t)krow0 * CC + c0;
        const __half* pb0 = (dual ? g_f1 : g_f0) + (size_t)col0 * CC + c0;
        uint32_t A0 = base + buf * STAGE, B0 = A0 + TILE_B, B1 = A0 + 2 * TILE_B;
        #pragma unroll
        for (int i = 0; i < 4; i++) cp16(A0 + dstoff[i], pa + srcoff[i]);
        #pragma unroll
        for (int i = 0; i < 4; i++) cp16(B0 + dstoff[i], pb0 + srcoff[i]);
        if (dual) {
            const __half* pb1 = g_f0 + (size_t)col0 * CC + c0;
            #pragma unroll
            for (int i = 0; i < 4; i++) cp16(B1 + dstoff[i], pb1 + srcoff[i]);
        }
        asm volatile("cp.async.commit_group;" ::: "memory");
    };

    issue(0, 0);

    #pragma unroll 1
    for (int ch = 0; ch < NCHUNK; ++ch) {
        asm volatile("cp.async.wait_group 0;" ::: "memory");   // chunk ch landed
        __syncthreads();                                        // all warps done with ch-1
        if (ch + 1 < NCHUNK) issue(ch + 1, (ch + 1) & 1);       // into buffer of ch-1

        uint32_t A0 = base + (ch & 1) * STAGE, B0t = A0 + TILE_B, B1t = A0 + 2 * TILE_B;
        bool dual = (ch >= 4);
        #pragma unroll
        for (int s = 0; s < 4; s++) {
            uint32_t sx = SWZ((uint32_t)(2 * s * 16));   // s-step delta (bits<7, swizzle-safe)
            uint32_t bf0[8], bf1[8];
            ldsm4(bf0,     B0t + (boff[0] ^ sx));
            ldsm4(bf0 + 4, B0t + (boff[1] ^ sx));
            if (dual) {
                ldsm4(bf1,     B1t + (boff[0] ^ sx));
                ldsm4(bf1 + 4, B1t + (boff[1] ^ sx));
            }
            #pragma unroll
            for (int mi = 0; mi < 4; mi++) {
                uint32_t af[4];
                ldsm4(af, A0 + (aoff[mi] ^ sx));
                #pragma unroll
                for (int ni = 0; ni < 4; ni++)
                    mma16816(acc[mi][ni], af, bf0 + 2 * ni);
                if (dual) {
                    #pragma unroll
                    for (int ni = 0; ni < 4; ni++)
                        mma16816(acc[mi][ni], af, bf1 + 2 * ni);
                }
            }
        }
    }

    // ---- epilogue: float2 streaming logits + partial (max,sumexp) ----
    #pragma unroll
    for (int ni = 0; ni < 4; ni++) {
        int j0 = warp_n * 32 + ni * 8 + 2 * (lane & 3);
        float fsq0 = s_fsq[j0], fsq1 = s_fsq[j0 + 1];
        long long cb0 = s_cbase[j0];
        float pm0 = -INFINITY, ps0 = 0.0f, pm1 = -INFINITY, ps1 = 0.0f;
        #pragma unroll
        for (int mi = 0; mi < 4; mi++) {
            #pragma unroll
            for (int rr = 0; rr < 2; rr++) {
                int krel = warp_m * 64 + mi * 16 + (lane >> 2) + rr * 8;
                float esq = s_esq[krel];
                float t0 = __fadd_rn(fsq0, __fmul_rn(-2.0f, acc[mi][ni][rr * 2 + 0]));
                float l0 = __fmul_rn(-30.0f, __fadd_rn(t0, esq));
                float t1 = __fadd_rn(fsq1, __fmul_rn(-2.0f, acc[mi][ni][rr * 2 + 1]));
                float l1 = __fmul_rn(-30.0f, __fadd_rn(t1, esq));
                float2 lv = make_float2(l0, l1);
                __stcs((float2*)&codes[cb0 + (long long)(krow0 + krel) * PP], lv);
                if (l0 > pm0) { ps0 = __fmaf_rn(ps0, __expf(pm0 - l0), 1.0f); pm0 = l0; }
                else          { ps0 += __expf(l0 - pm0); }
                if (l1 > pm1) { ps1 = __fmaf_rn(ps1, __expf(pm1 - l1), 1.0f); pm1 = l1; }
                else          { ps1 += __expf(l1 - pm1); }
            }
        }
        #pragma unroll
        for (int o = 4; o <= 16; o <<= 1) {
            float om = __shfl_xor_sync(0xFFFFFFFFu, pm0, o);
            float os = __shfl_xor_sync(0xFFFFFFFFu, ps0, o);
            if (om > pm0) { ps0 = ps0 * __expf(pm0 - om) + os; pm0 = om; }
            else          { ps0 += os * __expf(om - pm0); }
            om = __shfl_xor_sync(0xFFFFFFFFu, pm1, o);
            os = __shfl_xor_sync(0xFFFFFFFFu, ps1, o);
            if (om > pm1) { ps1 = ps1 * __expf(pm1 - om) + os; pm1 = om; }
            else          { ps1 += os * __expf(om - pm1); }
        }
        if ((lane >> 2) == 0) {
            s_rm[warp_m][j0] = pm0; s_rs[warp_m][j0] = ps0;
            s_rm[warp_m][j0 + 1] = pm1; s_rs[warp_m][j0 + 1] = ps1;
        }
    }
    __syncthreads();
    if (tid < NTT) {
        float m = -INFINITY, s = 0.0f;
        #pragma unroll
        for (int w = 0; w < 2; w++) {
            float mi = s_rm[w][tid], si = s_rs[w][tid];
            if (mi > m) { s = s * __expf(m - mi) + si; m = mi; }
            else        { s += si * __expf(mi - m); }
        }
        g_pm[blockIdx.y * COLS + col0 + tid] = m;
        g_ps[blockIdx.y * COLS + col0 + tid] = s;
    }
}

// ---------------- merge KSEG partials per column ----------------
__global__ void k_merge() {
    int col = blockIdx.x * 256 + threadIdx.x;
    if (col >= COLS) return;
    float m = -INFINITY, s = 0.0f;
    #pragma unroll 8
    for (int sp = 0; sp < KSEG; sp++) {
        float mi = g_pm[sp * COLS + col], si = g_ps[sp * COLS + col];
        if (mi > m) { s = s * __expf(m - mi) + si; m = mi; }
        else        { s += si * __expf(mi - m); }
    }
    g_colm[col] = m;
    g_colr[col] = 1.0f / s;
}

// ---------------- pass B: rescale + bow max (float4 streaming) ----------------
__global__ void k_phase2(float* __restrict__ out) {
    float* codes = out + CODES_OFF;
    float* bow   = out;
    int b = blockIdx.y, kc = blockIdx.x;
    int warp = threadIdx.x >> 5, lane = threadIdx.x & 31;

    __shared__ float4 sm4[49];
    __shared__ float4 sr4[49];
    float* smf = (float*)sm4;
    float* srf = (float*)sr4;
    for (int i = threadIdx.x; i < PP; i += 256) {
        smf[i] = g_colm[b * PP + i];
        srf[i] = g_colr[b * PP + i];
    }
    __syncthreads();

    #pragma unroll 2
    for (int rr = 0; rr < 32; ++rr) {
        int k = kc * 256 + warp * 32 + rr;
        float4* row = (float4*)(codes + ((size_t)b * KCODES + k) * PP);  // 784B rows, 16B-aligned
        float mx = 0.0f;
        #pragma unroll
        for (int it = 0; it < 2; it++) {
            int idx = it * 32 + lane;
            if (idx < 49) {
                float4 v = __ldcs(&row[idx]);
                float4 s = sm4[idx], r = sr4[idx];
                v.x = expf(__fadd_rn(v.x, -s.x)) * r.x;
                v.y = expf(__fadd_rn(v.y, -s.y)) * r.y;
                v.z = expf(__fadd_rn(v.z, -s.z)) * r.z;
                v.w = expf(__fadd_rn(v.w, -s.w)) * r.w;
                __stcs(&row[idx], v);
                mx = fmaxf(mx, fmaxf(fmaxf(v.x, v.y), fmaxf(v.z, v.w)));
            }
        }
        #pragma unroll
        for (int o = 16; o; o >>= 1) mx = fmaxf(mx, __shfl_xor_sync(0xFFFFFFFFu, mx, o));
        if (lane == 0) bow[(size_t)b * KCODES + k] = mx;
    }
}

__global__ void k_norm(float* __restrict__ out) {
    __shared__ float red[256];
    int b = blockIdx.x;
    float* r = out + (size_t)b * KCODES;
    float s = 0.0f;
    for (int i = threadIdx.x; i < KCODES; i += 256) s += fabsf(r[i]);
    red[threadIdx.x] = s;
    __syncthreads();
    for (int o = 128; o; o >>= 1) {
        if (threadIdx.x < o) red[threadIdx.x] += red[threadIdx.x + o];
        __syncthreads();
    }
    float tot = fmaxf(red[0], 1e-12f);
    for (int i = threadIdx.x; i < KCODES; i += 256) r[i] = r[i] / tot;
}

extern "C" void kernel_launch(void* const* d_in, const int* in_sizes, int n_in,
                              void* d_out, int out_size) {
    const float* feat = (const float*)d_in[0];   // [32,256,16,16]
    const float* emb  = (const float*)d_in[1];   // [8192,256]
    float* out = (float*)d_out;

    cudaFuncSetAttribute(k_mma, cudaFuncAttributeMaxDynamicSharedMemorySize, DSMEM);

    k_prep_emb<<<KCODES / 8, 256>>>(emb);                        // 1
    k_prep_f<<<dim3(COLS / 32, CC / 32), dim3(32, 32)>>>(feat);  // 2
    k_fsq<<<BB, 256>>>(feat);                                    // 3
    k_mma<<<dim3(COLS / NTT, KCODES / MT), 256, DSMEM>>>(out);   // 4 (profiled slot)
    k_merge<<<(COLS + 255) / 256, 256>>>();                      // 5
    k_phase2<<<dim3(KCODES / 256, BB), 256>>>(out);              // 6
    k_norm<<<BB, 256>>>(out);                                    // 7
}

// round 14
// speedup vs baseline: 1.0313x; 1.0313x over previous
#include <cuda_runtime.h>
#include <cuda_fp16.h>
#include <math.h>
#include <stdint.h>

#define BB   32
#define CC   256
#define HCH  14
#define PP   196
#define KCODES 8192
#define COLS 6272
#define BOW_ELEMS (BB*KCODES)
#define CODES_OFF BOW_ELEMS

#define KC 64                  // fp16 per chunk row = 128B (SW128)
#define NCHUNK 12              // 3 terms * (256/64)
#define MT 128                 // M rows per CTA
#define NTT 128                // N cols per CTA
#define A_BYTES (MT*128)       // 16384
#define B_BYTES (NTT*128)      // 16384
#define STAGE (A_BYTES + B_BYTES)   // 32768
#define NSTAGE 3
#define DSMEM (NSTAGE*STAGE + 1024)
#define KSEG (KCODES/MT)       // 64

// ---------------- scratch ----------------
__device__ __half g_e0[KCODES*CC], g_e1[KCODES*CC];
__device__ __half g_f0[COLS*CC],   g_f1[COLS*CC];
__device__ float g_esq[KCODES];
__device__ float g_fsq[COLS];
__device__ float g_pm[KSEG*COLS];
__device__ float g_ps[KSEG*COLS];
__device__ float g_colm[COLS];
__device__ float g_colr[COLS];

// ---------------- helpers ----------------
__device__ __forceinline__ uint32_t s2u(const void* p) {
    uint32_t a;
    asm("{ .reg .u64 t; cvta.to.shared.u64 t, %1; cvt.u32.u64 %0, t; }" : "=r"(a) : "l"(p));
    return a;
}
#define SWZ(o) ((o) ^ (((o) >> 3) & 0x70))
__device__ __forceinline__ void cp16(uint32_t dst, const void* src) {
    asm volatile("cp.async.cg.shared.global [%0], [%1], 16;" :: "r"(dst), "l"(src));
}
__device__ __forceinline__ void ldsm4(uint32_t* r, uint32_t addr) {
    asm volatile("ldmatrix.sync.aligned.m8n8.x4.shared.b16 {%0,%1,%2,%3}, [%4];"
                 : "=r"(r[0]), "=r"(r[1]), "=r"(r[2]), "=r"(r[3]) : "r"(addr));
}
__device__ __forceinline__ void mma16816(float* c, const uint32_t* a, const uint32_t* b) {
    asm volatile(
        "mma.sync.aligned.m16n8k16.row.col.f32.f16.f16.f32 "
        "{%0,%1,%2,%3}, {%4,%5,%6,%7}, {%8,%9}, {%0,%1,%2,%3};"
        : "+f"(c[0]), "+f"(c[1]), "+f"(c[2]), "+f"(c[3])
        : "r"(a[0]), "r"(a[1]), "r"(a[2]), "r"(a[3]), "r"(b[0]), "r"(b[1]));
}

// ---------------- prep: embedding fp16 hi/lo split + e_sq (warp per row) ----
__global__ void k_prep_emb(const float* __restrict__ emb) {
    int warp = (blockIdx.x * blockDim.x + threadIdx.x) >> 5;
    int lane = threadIdx.x & 31;
    if (warp >= KCODES) return;
    const float* r = emb + (size_t)warp * CC;
    double s = 0.0;
    #pragma unroll
    for (int i = 0; i < CC / 32; i++) {
        int c = lane + i * 32;
        float v = r[c];
        s += (double)v * (double)v;
        __half h = __float2half_rn(v);
        float r1 = v - __half2float(h);
        size_t o = (size_t)warp * CC + c;
        g_e0[o] = h; g_e1[o] = __float2half_rn(r1);
    }
    #pragma unroll
    for (int o = 16; o; o >>= 1) s += __shfl_xor_sync(0xFFFFFFFFu, s, o);
    if (lane == 0) g_esq[warp] = (float)s;
}

// crop + transpose features -> [col][c] fp16 hi/lo split
__global__ void k_prep_f(const float* __restrict__ feat) {
    __shared__ float tile[32][33];
    int tx = threadIdx.x, ty = threadIdx.y;
    int col = blockIdx.x * 32 + tx;
    int c   = blockIdx.y * 32 + ty;
    int b = col / PP, p = col - b * PP;
    int y = p / HCH + 1, x = p - (y - 1) * HCH + 1;
    tile[ty][tx] = feat[((size_t)(b * CC + c) * 16 + y) * 16 + x];
    __syncthreads();
    int colw = blockIdx.x * 32 + ty;
    int cw   = blockIdx.y * 32 + tx;
    float v = tile[tx][ty];
    __half h = __float2half_rn(v);
    float r1 = v - __half2float(h);
    size_t o = (size_t)colw * CC + cw;
    g_f0[o] = h; g_f1[o] = __float2half_rn(r1);
}

// f_sq: block per batch, thread = pixel, 4 fp64 accumulators for MLP
__global__ void k_fsq(const float* __restrict__ feat) {
    int b = blockIdx.x, t = threadIdx.x;          // t = y*16+x
    const float* fp = feat + (size_t)b * CC * 256 + t;
    double s0 = 0.0, s1 = 0.0, s2 = 0.0, s3 = 0.0;
    #pragma unroll 16
    for (int c = 0; c < CC; c += 4) {
        float v0 = fp[(size_t)(c + 0) * 256];
        float v1 = fp[(size_t)(c + 1) * 256];
        float v2 = fp[(size_t)(c + 2) * 256];
        float v3 = fp[(size_t)(c + 3) * 256];
        s0 += (double)v0 * v0; s1 += (double)v1 * v1;
        s2 += (double)v2 * v2; s3 += (double)v3 * v3;
    }
    double s = (s0 + s1) + (s2 + s3);
    int y = t >> 4, x = t & 15;
    if (y >= 1 && y <= 14 && x >= 1 && x <= 14)
        g_fsq[b * PP + (y - 1) * HCH + (x - 1)] = (float)s;
}

// ---------------------------------------------------------------------------
// Warp-MMA GEMM: CTA 128x128, 8 warps, warp tile 64x32, 2 CTAs/SM.
// 3-term fp16x2 emulation (h0b1, h1b0, h0b0 — small to large), 3-stage
// cp.async pipeline, fragment double-buffer, SW128 smem.
// Epilogue: float2 streaming logits + per-(ktile,col) partial (max, sumexp).
// ---------------------------------------------------------------------------
__global__ __launch_bounds__(256, 2) void k_mma(float* __restrict__ out) {
    extern __shared__ char dsm[];
    __shared__ float     s_fsq[NTT];
    __shared__ float     s_esq[MT];
    __shared__ long long s_cbase[NTT];
    __shared__ float     s_rm[2][NTT];
    __shared__ float     s_rs[2][NTT];

    int tid = threadIdx.x, lane = tid & 31, wid = tid >> 5;
    int warp_m = wid >> 2, warp_n = wid & 3;     // warp tile: 64 m x 32 n
    int col0 = blockIdx.x * NTT, krow0 = blockIdx.y * MT;
    float* codes = out + CODES_OFF;
    uint32_t base = (s2u(dsm) + 1023u) & ~1023u;

    if (tid < NTT) {
        int col = col0 + tid;
        s_fsq[tid] = g_fsq[col];
        int b = col / PP, p = col - b * PP;
        s_cbase[tid] = (long long)b * KCODES * PP + p;
    }
    if (tid < MT) s_esq[tid] = g_esq[krow0 + tid];

    float acc[4][4][4];                          // [mi][ni][quad]
    #pragma unroll
    for (int mi = 0; mi < 4; mi++)
        #pragma unroll
        for (int ni = 0; ni < 4; ni++)
            #pragma unroll
            for (int q = 0; q < 4; q++) acc[mi][ni][q] = 0.0f;

    int rA = lane & 15, csA = lane >> 4;
    int rB = ((lane >> 4) << 3) + (lane & 7), csB = (lane >> 3) & 1;

    // hoisted per-thread smem read offsets (relative to tile base)
    uint32_t aoff[4], boff[2];
    #pragma unroll
    for (int mi = 0; mi < 4; mi++)
        aoff[mi] = SWZ((uint32_t)((warp_m * 64 + mi * 16 + rA) * 128 + csA * 16));
    boff[0] = SWZ((uint32_t)((warp_n * 32 + rB) * 128 + csB * 16));
    boff[1] = SWZ((uint32_t)((warp_n * 32 + 16 + rB) * 128 + csB * 16));

    // hoisted per-thread load addressing (invariant across chunks)
    uint32_t dstoff[4];
    size_t   srcoff[4];
    #pragma unroll
    for (int i = 0; i < 4; i++) {
        int u = tid + i * 256, r = u >> 3, g = u & 7;
        dstoff[i] = SWZ((uint32_t)(r * 128 + g * 16));
        srcoff[i] = (size_t)r * CC + g * 8;
    }

    auto issue = [&](int ch, int buf) {
        int t = ch >> 2, c0 = (ch & 3) * KC;
        // term table (small -> large): t0:(e1,f0)  t1:(e0,f1)  t2:(e0,f0)
        const __half* pa = ((t == 0) ? g_e1 : g_e0) + (size_t)krow0 * CC + c0;
        const __half* pb = ((t == 1) ? g_f1 : g_f0) + (size_t)col0 * CC + c0;
        uint32_t A0 = base + buf * STAGE, B0 = A0 + A_BYTES;
        #pragma unroll
        for (int i = 0; i < 4; i++) cp16(A0 + dstoff[i], pa + srcoff[i]);
        #pragma unroll
        for (int i = 0; i < 4; i++) cp16(B0 + dstoff[i], pb + srcoff[i]);
        asm volatile("cp.async.commit_group;" ::: "memory");
    };

    issue(0, 0);
    issue(1, 1);

    #pragma unroll 1
    for (int ch = 0; ch < NCHUNK; ++ch) {
        if (ch < NCHUNK - 1) asm volatile("cp.async.wait_group 1;" ::: "memory");
        else                 asm volatile("cp.async.wait_group 0;" ::: "memory");
        __syncthreads();
        // buffer (ch+2)%NSTAGE == (ch-1)%NSTAGE is free (computed before barrier)
        if (ch + 2 < NCHUNK) issue(ch + 2, (ch + 2) % NSTAGE);

        uint32_t A0 = base + (ch % NSTAGE) * STAGE, B0 = A0 + A_BYTES;

        // fragment double-buffered inner loop
        uint32_t bf[2][8], af[2][4];
        ldsm4(bf[0],     B0 + (boff[0] ^ 0u));
        ldsm4(bf[0] + 4, B0 + (boff[1] ^ 0u));
        ldsm4(af[0],     A0 + (aoff[0] ^ 0u));
        #pragma unroll
        for (int s = 0; s < 4; s++) {
            int cs = s & 1, ns = cs ^ 1;
            uint32_t sx  = SWZ((uint32_t)(2 * s * 16));        // s-step delta (bits<7, swizzle-safe)
            uint32_t sxn = SWZ((uint32_t)(2 * (s + 1) * 16));
            if (s < 3) {
                ldsm4(bf[ns],     B0 + (boff[0] ^ sxn));
                ldsm4(bf[ns] + 4, B0 + (boff[1] ^ sxn));
            }
            #pragma unroll
            for (int mi = 0; mi < 4; mi++) {
                int cm = mi & 1, nm = cm ^ 1;
                if (mi < 3)      ldsm4(af[nm], A0 + (aoff[mi + 1] ^ sx));
                else if (s < 3)  ldsm4(af[nm], A0 + (aoff[0] ^ sxn));
                #pragma unroll
                for (int ni = 0; ni < 4; ni++)
                    mma16816(acc[mi][ni], af[cm], bf[cs] + 2 * ni);
            }
        }
    }

    // ---- epilogue: float2 streaming logits + partial (max,sumexp) ----
    #pragma unroll
    for (int ni = 0; ni < 4; ni++) {
        int j0 = warp_n * 32 + ni * 8 + 2 * (lane & 3);
        float fsq0 = s_fsq[j0], fsq1 = s_fsq[j0 + 1];
        long long cb0 = s_cbase[j0];
        float pm0 = -INFINITY, ps0 = 0.0f, pm1 = -INFINITY, ps1 = 0.0f;
        #pragma unroll
        for (int mi = 0; mi < 4; mi++) {
            #pragma unroll
            for (int rr = 0; rr < 2; rr++) {
                int krel = warp_m * 64 + mi * 16 + (lane >> 2) + rr * 8;
                float esq = s_esq[krel];
                float t0 = __fadd_rn(fsq0, __fmul_rn(-2.0f, acc[mi][ni][rr * 2 + 0]));
                float l0 = __fmul_rn(-30.0f, __fadd_rn(t0, esq));
                float t1 = __fadd_rn(fsq1, __fmul_rn(-2.0f, acc[mi][ni][rr * 2 + 1]));
                float l1 = __fmul_rn(-30.0f, __fadd_rn(t1, esq));
                float2 lv = make_float2(l0, l1);
                __stcs((float2*)&codes[cb0 + (long long)(krow0 + krel) * PP], lv);
                if (l0 > pm0) { ps0 = __fmaf_rn(ps0, __expf(pm0 - l0), 1.0f); pm0 = l0; }
                else          { ps0 += __expf(l0 - pm0); }
                if (l1 > pm1) { ps1 = __fmaf_rn(ps1, __expf(pm1 - l1), 1.0f); pm1 = l1; }
                else          { ps1 += __expf(l1 - pm1); }
            }
        }
        #pragma unroll
        for (int o = 4; o <= 16; o <<= 1) {
            float om = __shfl_xor_sync(0xFFFFFFFFu, pm0, o);
            float os = __shfl_xor_sync(0xFFFFFFFFu, ps0, o);
            if (om > pm0) { ps0 = ps0 * __expf(pm0 - om) + os; pm0 = om; }
            else          { ps0 += os * __expf(om - pm0); }
            om = __shfl_xor_sync(0xFFFFFFFFu, pm1, o);
            os = __shfl_xor_sync(0xFFFFFFFFu, ps1, o);
            if (om > pm1) { ps1 = ps1 * __expf(pm1 - om) + os; pm1 = om; }
            else          { ps1 += os * __expf(om - pm1); }
        }
        if ((lane >> 2) == 0) {
            s_rm[warp_m][j0] = pm0; s_rs[warp_m][j0] = ps0;
            s_rm[warp_m][j0 + 1] = pm1; s_rs[warp_m][j0 + 1] = ps1;
        }
    }
    __syncthreads();
    if (tid < NTT) {
        float m = -INFINITY, s = 0.0f;
        #pragma unroll
        for (int w = 0; w < 2; w++) {
            float mi = s_rm[w][tid], si = s_rs[w][tid];
            if (mi > m) { s = s * __expf(m - mi) + si; m = mi; }
            else        { s += si * __expf(mi - m); }
        }
        g_pm[blockIdx.y * COLS + col0 + tid] = m;
        g_ps[blockIdx.y * COLS + col0 + tid] = s;
    }
}

// ---------------- merge KSEG partials per column ----------------
__global__ void k_merge() {
    int col = blockIdx.x * 256 + threadIdx.x;
    if (col >= COLS) return;
    float m = -INFINITY, s = 0.0f;
    #pragma unroll 8
    for (int sp = 0; sp < KSEG; sp++) {
        float mi = g_pm[sp * COLS + col], si = g_ps[sp * COLS + col];
        if (mi > m) { s = s * __expf(m - mi) + si; m = mi; }
        else        { s += si * __expf(mi - m); }
    }
    g_colm[col] = m;
    g_colr[col] = 1.0f / s;
}

// ---------------- pass B: rescale + bow max (float4 streaming) ----------------
__global__ void k_phase2(float* __restrict__ out) {
    float* codes = out + CODES_OFF;
    float* bow   = out;
    int b = blockIdx.y, kc = blockIdx.x;
    int warp = threadIdx.x >> 5, lane = threadIdx.x & 31;

    __shared__ float4 sm4[49];
    __shared__ float4 sr4[49];
    float* smf = (float*)sm4;
    float* srf = (float*)sr4;
    for (int i = threadIdx.x; i < PP; i += 256) {
        smf[i] = g_colm[b * PP + i];
        srf[i] = g_colr[b * PP + i];
    }
    __syncthreads();

    #pragma unroll 2
    for (int rr = 0; rr < 32; ++rr) {
        int k = kc * 256 + warp * 32 + rr;
        float4* row = (float4*)(codes + ((size_t)b * KCODES + k) * PP);  // 784B rows, 16B-aligned
        float mx = 0.0f;
        #pragma unroll
        for (int it = 0; it < 2; it++) {
            int idx = it * 32 + lane;
            if (idx < 49) {
                float4 v = __ldcs(&row[idx]);
                float4 s = sm4[idx], r = sr4[idx];
                v.x = expf(__fadd_rn(v.x, -s.x)) * r.x;
                v.y = expf(__fadd_rn(v.y, -s.y)) * r.y;
                v.z = expf(__fadd_rn(v.z, -s.z)) * r.z;
                v.w = expf(__fadd_rn(v.w, -s.w)) * r.w;
                __stcs(&row[idx], v);
                mx = fmaxf(mx, fmaxf(fmaxf(v.x, v.y), fmaxf(v.z, v.w)));
            }
        }
        #pragma unroll
        for (int o = 16; o; o >>= 1) mx = fmaxf(mx, __shfl_xor_sync(0xFFFFFFFFu, mx, o));
        if (lane == 0) bow[(size_t)b * KCODES + k] = mx;
    }
}

__global__ void k_norm(float* __restrict__ out) {
    __shared__ float red[256];
    int b = blockIdx.x;
    float* r = out + (size_t)b * KCODES;
    float s = 0.0f;
    for (int i = threadIdx.x; i < KCODES; i += 256) s += fabsf(r[i]);
    red[threadIdx.x] = s;
    __syncthreads();
    for (int o = 128; o; o >>= 1) {
        if (threadIdx.x < o) red[threadIdx.x] += red[threadIdx.x + o];
        __syncthreads();
    }
    float tot = fmaxf(red[0], 1e-12f);
    for (int i = threadIdx.x; i < KCODES; i += 256) r[i] = r[i] / tot;
}

extern "C" void kernel_launch(void* const* d_in, const int* in_sizes, int n_in,
                              void* d_out, int out_size) {
    const float* feat = (const float*)d_in[0];   // [32,256,16,16]
    const float* emb  = (const float*)d_in[1];   // [8192,256]
    float* out = (float*)d_out;

    cudaFuncSetAttribute(k_mma, cudaFuncAttributeMaxDynamicSharedMemorySize, DSMEM);

    k_prep_emb<<<KCODES / 8, 256>>>(emb);                        // 1
    k_prep_f<<<dim3(COLS / 32, CC / 32), dim3(32, 32)>>>(feat);  // 2
    k_fsq<<<BB, 256>>>(feat);                                    // 3
    k_mma<<<dim3(COLS / NTT, KCODES / MT), 256, DSMEM>>>(out);   // 4 (profiled slot)
    k_merge<<<(COLS + 255) / 256, 256>>>();                      // 5
    k_phase2<<<dim3(KCODES / 256, BB), 256>>>(out);              // 6
    k_norm<<<BB, 256>>>(out);                                    // 7
}

// round 15
// speedup vs baseline: 1.0573x; 1.0252x over previous
#include <cuda_runtime.h>
#include <cuda_fp16.h>
#include <math.h>
#include <stdint.h>

#define BB   32
#define CC   256
#define HCH  14
#define PP   196
#define KCODES 8192
#define COLS 6272
#define BOW_ELEMS (BB*KCODES)
#define CODES_OFF BOW_ELEMS

#define KC 64                  // fp16 per chunk row = 128B (SW128)
#define NCHUNK 12              // 3 terms * (256/64)
#define MT 128                 // M rows per CTA
#define NTT 128                // N cols per CTA
#define A_BYTES (MT*128)       // 16384
#define B_BYTES (NTT*128)      // 16384
#define STAGE (A_BYTES + B_BYTES)   // 32768
#define NSTAGE 3
#define DSMEM (NSTAGE*STAGE + 1024)
#define KSEG (KCODES/MT)       // 64
#define CBLK (CC/32)           // 8 fsq partial slabs

// ---------------- scratch ----------------
__device__ __half g_e0[KCODES*CC], g_e1[KCODES*CC];
__device__ __half g_f0[COLS*CC],   g_f1[COLS*CC];
__device__ float  g_esq[KCODES];
__device__ float  g_fsq[COLS];
__device__ double g_fsp[CBLK*COLS];   // fsq partial sums (fp64, deterministic)
__device__ float  g_pm[KSEG*COLS];
__device__ float  g_ps[KSEG*COLS];
__device__ float  g_colm[COLS];
__device__ float  g_colr[COLS];

// ---------------- helpers ----------------
__device__ __forceinline__ uint32_t s2u(const void* p) {
    uint32_t a;
    asm("{ .reg .u64 t; cvta.to.shared.u64 t, %1; cvt.u32.u64 %0, t; }" : "=r"(a) : "l"(p));
    return a;
}
#define SWZ(o) ((o) ^ (((o) >> 3) & 0x70))
__device__ __forceinline__ void cp16(uint32_t dst, const void* src) {
    asm volatile("cp.async.cg.shared.global [%0], [%1], 16;" :: "r"(dst), "l"(src));
}
__device__ __forceinline__ void ldsm4(uint32_t* r, uint32_t addr) {
    asm volatile("ldmatrix.sync.aligned.m8n8.x4.shared.b16 {%0,%1,%2,%3}, [%4];"
                 : "=r"(r[0]), "=r"(r[1]), "=r"(r[2]), "=r"(r[3]) : "r"(addr));
}
__device__ __forceinline__ void mma16816(float* c, const uint32_t* a, const uint32_t* b) {
    asm volatile(
        "mma.sync.aligned.m16n8k16.row.col.f32.f16.f16.f32 "
        "{%0,%1,%2,%3}, {%4,%5,%6,%7}, {%8,%9}, {%0,%1,%2,%3};"
        : "+f"(c[0]), "+f"(c[1]), "+f"(c[2]), "+f"(c[3])
        : "r"(a[0]), "r"(a[1]), "r"(a[2]), "r"(a[3]), "r"(b[0]), "r"(b[1]));
}

// ---------------- prep: embedding fp16 hi/lo split + e_sq (warp per row) ----
__global__ void k_prep_emb(const float* __restrict__ emb) {
    int warp = (blockIdx.x * blockDim.x + threadIdx.x) >> 5;
    int lane = threadIdx.x & 31;
    if (warp >= KCODES) return;
    const float* r = emb + (size_t)warp * CC;
    double s = 0.0;
    #pragma unroll
    for (int i = 0; i < CC / 32; i++) {
        int c = lane + i * 32;
        float v = r[c];
        s += (double)v * (double)v;
        __half h = __float2half_rn(v);
        float r1 = v - __half2float(h);
        size_t o = (size_t)warp * CC + c;
        g_e0[o] = h; g_e1[o] = __float2half_rn(r1);
    }
    #pragma unroll
    for (int o = 16; o; o >>= 1) s += __shfl_xor_sync(0xFFFFFFFFu, s, o);
    if (lane == 0) g_esq[warp] = (float)s;
}

// crop + transpose features -> [col][c] fp16 hi/lo split; also fp64 fsq partials
__global__ void k_prep_f(const float* __restrict__ feat) {
    __shared__ float tile[32][33];
    int tx = threadIdx.x, ty = threadIdx.y;
    int col = blockIdx.x * 32 + tx;
    int c   = blockIdx.y * 32 + ty;
    int b = col / PP, p = col - b * PP;
    int y = p / HCH + 1, x = p - (y - 1) * HCH + 1;
    tile[ty][tx] = feat[((size_t)(b * CC + c) * 16 + y) * 16 + x];
    __syncthreads();
    int colw = blockIdx.x * 32 + ty;
    int cw   = blockIdx.y * 32 + tx;
    float v = tile[tx][ty];
    __half h = __float2half_rn(v);
    float r1 = v - __half2float(h);
    size_t o = (size_t)colw * CC + cw;
    g_f0[o] = h; g_f1[o] = __float2half_rn(r1);
    // fsq partial: warp (fixed ty = colw) reduces v^2 over its 32 channels
    double sq = (double)v * (double)v;
    #pragma unroll
    for (int ofs = 16; ofs; ofs >>= 1) sq += __shfl_xor_sync(0xFFFFFFFFu, sq, ofs);
    if (tx == 0) g_fsp[blockIdx.y * COLS + colw] = sq;
}

// merge the 8 fp64 fsq partials per column (fixed order -> deterministic)
__global__ void k_fsqm() {
    int col = blockIdx.x * 256 + threadIdx.x;
    if (col >= COLS) return;
    double s = 0.0;
    #pragma unroll
    for (int i = 0; i < CBLK; i++) s += g_fsp[i * COLS + col];
    g_fsq[col] = (float)s;
}

// ---------------------------------------------------------------------------
// Warp-MMA GEMM: CTA 128x128, 8 warps, warp tile 64x32, 2 CTAs/SM.
// 3-term fp16x2 emulation (h0b1, h1b0, h0b0 — small to large), 3-stage
// cp.async pipeline, fragment double-buffer, SW128 smem.  (UNCHANGED from
// verified 402us baseline.)
// ---------------------------------------------------------------------------
__global__ __launch_bounds__(256, 2) void k_mma(float* __restrict__ out) {
    extern __shared__ char dsm[];
    __shared__ float     s_fsq[NTT];
    __shared__ float     s_esq[MT];
    __shared__ long long s_cbase[NTT];
    __shared__ float     s_rm[2][NTT];
    __shared__ float     s_rs[2][NTT];

    int tid = threadIdx.x, lane = tid & 31, wid = tid >> 5;
    int warp_m = wid >> 2, warp_n = wid & 3;     // warp tile: 64 m x 32 n
    int col0 = blockIdx.x * NTT, krow0 = blockIdx.y * MT;
    float* codes = out + CODES_OFF;
    uint32_t base = (s2u(dsm) + 1023u) & ~1023u;

    if (tid < NTT) {
        int col = col0 + tid;
        s_fsq[tid] = g_fsq[col];
        int b = col / PP, p = col - b * PP;
        s_cbase[tid] = (long long)b * KCODES * PP + p;
    }
    if (tid < MT) s_esq[tid] = g_esq[krow0 + tid];

    float acc[4][4][4];                          // [mi][ni][quad]
    #pragma unroll
    for (int mi = 0; mi < 4; mi++)
        #pragma unroll
        for (int ni = 0; ni < 4; ni++)
            #pragma unroll
            for (int q = 0; q < 4; q++) acc[mi][ni][q] = 0.0f;

    int rA = lane & 15, csA = lane >> 4;
    int rB = ((lane >> 4) << 3) + (lane & 7), csB = (lane >> 3) & 1;

    uint32_t aoff[4], boff[2];
    #pragma unroll
    for (int mi = 0; mi < 4; mi++)
        aoff[mi] = SWZ((uint32_t)((warp_m * 64 + mi * 16 + rA) * 128 + csA * 16));
    boff[0] = SWZ((uint32_t)((warp_n * 32 + rB) * 128 + csB * 16));
    boff[1] = SWZ((uint32_t)((warp_n * 32 + 16 + rB) * 128 + csB * 16));

    uint32_t dstoff[4];
    size_t   srcoff[4];
    #pragma unroll
    for (int i = 0; i < 4; i++) {
        int u = tid + i * 256, r = u >> 3, g = u & 7;
        dstoff[i] = SWZ((uint32_t)(r * 128 + g * 16));
        srcoff[i] = (size_t)r * CC + g * 8;
    }

    auto issue = [&](int ch, int buf) {
        int t = ch >> 2, c0 = (ch & 3) * KC;
        // term table (small -> large): t0:(e1,f0)  t1:(e0,f1)  t2:(e0,f0)
        const __half* pa = ((t == 0) ? g_e1 : g_e0) + (size_t)krow0 * CC + c0;
        const __half* pb = ((t == 1) ? g_f1 : g_f0) + (size_t)col0 * CC + c0;
        uint32_t A0 = base + buf * STAGE, B0 = A0 + A_BYTES;
        #pragma unroll
        for (int i = 0; i < 4; i++) cp16(A0 + dstoff[i], pa + srcoff[i]);
        #pragma unroll
        for (int i = 0; i < 4; i++) cp16(B0 + dstoff[i], pb + srcoff[i]);
        asm volatile("cp.async.commit_group;" ::: "memory");
    };

    issue(0, 0);
    issue(1, 1);

    #pragma unroll 1
    for (int ch = 0; ch < NCHUNK; ++ch) {
        if (ch < NCHUNK - 1) asm volatile("cp.async.wait_group 1;" ::: "memory");
        else                 asm volatile("cp.async.wait_group 0;" ::: "memory");
        __syncthreads();
        if (ch + 2 < NCHUNK) issue(ch + 2, (ch + 2) % NSTAGE);

        uint32_t A0 = base + (ch % NSTAGE) * STAGE, B0 = A0 + A_BYTES;

        uint32_t bf[2][8], af[2][4];
        ldsm4(bf[0],     B0 + (boff[0] ^ 0u));
        ldsm4(bf[0] + 4, B0 + (boff[1] ^ 0u));
        ldsm4(af[0],     A0 + (aoff[0] ^ 0u));
        #pragma unroll
        for (int s = 0; s < 4; s++) {
            int cs = s & 1, ns = cs ^ 1;
            uint32_t sx  = SWZ((uint32_t)(2 * s * 16));
            uint32_t sxn = SWZ((uint32_t)(2 * (s + 1) * 16));
            if (s < 3) {
                ldsm4(bf[ns],     B0 + (boff[0] ^ sxn));
                ldsm4(bf[ns] + 4, B0 + (boff[1] ^ sxn));
            }
            #pragma unroll
            for (int mi = 0; mi < 4; mi++) {
                int cm = mi & 1, nm = cm ^ 1;
                if (mi < 3)      ldsm4(af[nm], A0 + (aoff[mi + 1] ^ sx));
                else if (s < 3)  ldsm4(af[nm], A0 + (aoff[0] ^ sxn));
                #pragma unroll
                for (int ni = 0; ni < 4; ni++)
                    mma16816(acc[mi][ni], af[cm], bf[cs] + 2 * ni);
            }
        }
    }

    // ---- epilogue: float2 streaming logits + partial (max,sumexp) ----
    #pragma unroll
    for (int ni = 0; ni < 4; ni++) {
        int j0 = warp_n * 32 + ni * 8 + 2 * (lane & 3);
        float fsq0 = s_fsq[j0], fsq1 = s_fsq[j0 + 1];
        long long cb0 = s_cbase[j0];
        float pm0 = -INFINITY, ps0 = 0.0f, pm1 = -INFINITY, ps1 = 0.0f;
        #pragma unroll
        for (int mi = 0; mi < 4; mi++) {
            #pragma unroll
            for (int rr = 0; rr < 2; rr++) {
                int krel = warp_m * 64 + mi * 16 + (lane >> 2) + rr * 8;
                float esq = s_esq[krel];
                float t0 = __fadd_rn(fsq0, __fmul_rn(-2.0f, acc[mi][ni][rr * 2 + 0]));
                float l0 = __fmul_rn(-30.0f, __fadd_rn(t0, esq));
                float t1 = __fadd_rn(fsq1, __fmul_rn(-2.0f, acc[mi][ni][rr * 2 + 1]));
                float l1 = __fmul_rn(-30.0f, __fadd_rn(t1, esq));
                float2 lv = make_float2(l0, l1);
                __stcs((float2*)&codes[cb0 + (long long)(krow0 + krel) * PP], lv);
                if (l0 > pm0) { ps0 = __fmaf_rn(ps0, __expf(pm0 - l0), 1.0f); pm0 = l0; }
                else          { ps0 += __expf(l0 - pm0); }
                if (l1 > pm1) { ps1 = __fmaf_rn(ps1, __expf(pm1 - l1), 1.0f); pm1 = l1; }
                else          { ps1 += __expf(l1 - pm1); }
            }
        }
        #pragma unroll
        for (int o = 4; o <= 16; o <<= 1) {
            float om = __shfl_xor_sync(0xFFFFFFFFu, pm0, o);
            float os = __shfl_xor_sync(0xFFFFFFFFu, ps0, o);
            if (om > pm0) { ps0 = ps0 * __expf(pm0 - om) + os; pm0 = om; }
            else          { ps0 += os * __expf(om - pm0); }
            om = __shfl_xor_sync(0xFFFFFFFFu, pm1, o);
            os = __shfl_xor_sync(0xFFFFFFFFu, ps1, o);
            if (om > pm1) { ps1 = ps1 * __expf(pm1 - om) + os; pm1 = om; }
            else          { ps1 += os * __expf(om - pm1); }
        }
        if ((lane >> 2) == 0) {
            s_rm[warp_m][j0] = pm0; s_rs[warp_m][j0] = ps0;
            s_rm[warp_m][j0 + 1] = pm1; s_rs[warp_m][j0 + 1] = ps1;
        }
    }
    __syncthreads();
    if (tid < NTT) {
        float m = -INFINITY, s = 0.0f;
        #pragma unroll
        for (int w = 0; w < 2; w++) {
            float mi = s_rm[w][tid], si = s_rs[w][tid];
            if (mi > m) { s = s * __expf(m - mi) + si; m = mi; }
            else        { s += si * __expf(mi - m); }
        }
        g_pm[blockIdx.y * COLS + col0 + tid] = m;
        g_ps[blockIdx.y * COLS + col0 + tid] = s;
    }
}

// ---------------- merge KSEG partials per column ----------------
__global__ void k_merge() {
    int col = blockIdx.x * 256 + threadIdx.x;
    if (col >= COLS) return;
    float m = -INFINITY, s = 0.0f;
    #pragma unroll 8
    for (int sp = 0; sp < KSEG; sp++) {
        float mi = g_pm[sp * COLS + col], si = g_ps[sp * COLS + col];
        if (mi > m) { s = s * __expf(m - mi) + si; m = mi; }
        else        { s += si * __expf(mi - m); }
    }
    g_colm[col] = m;
    g_colr[col] = 1.0f / s;
}

// ---------------- pass B: rescale + bow max (float4 streaming, fast exp) ----
__global__ void k_phase2(float* __restrict__ out) {
    float* codes = out + CODES_OFF;
    float* bow   = out;
    int b = blockIdx.y, kc = blockIdx.x;
    int warp = threadIdx.x >> 5, lane = threadIdx.x & 31;

    __shared__ float4 sm4[49];
    __shared__ float4 sr4[49];
    float* smf = (float*)sm4;
    float* srf = (float*)sr4;
    for (int i = threadIdx.x; i < PP; i += 256) {
        smf[i] = g_colm[b * PP + i];
        srf[i] = g_colr[b * PP + i];
    }
    __syncthreads();

    #pragma unroll 2
    for (int rr = 0; rr < 32; ++rr) {
        int k = kc * 256 + warp * 32 + rr;
        float4* row = (float4*)(codes + ((size_t)b * KCODES + k) * PP);  // 784B rows, 16B-aligned
        float mx = 0.0f;
        #pragma unroll
        for (int it = 0; it < 2; it++) {
            int idx = it * 32 + lane;
            if (idx < 49) {
                float4 v = __ldcs(&row[idx]);
                float4 s = sm4[idx], r = sr4[idx];
                v.x = __expf(__fadd_rn(v.x, -s.x)) * r.x;
                v.y = __expf(__fadd_rn(v.y, -s.y)) * r.y;
                v.z = __expf(__fadd_rn(v.z, -s.z)) * r.z;
                v.w = __expf(__fadd_rn(v.w, -s.w)) * r.w;
                __stcs(&row[idx], v);
                mx = fmaxf(mx, fmaxf(fmaxf(v.x, v.y), fmaxf(v.z, v.w)));
            }
        }
        #pragma unroll
        for (int o = 16; o; o >>= 1) mx = fmaxf(mx, __shfl_xor_sync(0xFFFFFFFFu, mx, o));
        if (lane == 0) bow[(size_t)b * KCODES + k] = mx;
    }
}

__global__ void k_norm(float* __restrict__ out) {
    __shared__ float red[256];
    int b = blockIdx.x;
    float* r = out + (size_t)b * KCODES;
    float s = 0.0f;
    for (int i = threadIdx.x; i < KCODES; i += 256) s += fabsf(r[i]);
    red[threadIdx.x] = s;
    __syncthreads();
    for (int o = 128; o; o >>= 1) {
        if (threadIdx.x < o) red[threadIdx.x] += red[threadIdx.x + o];
        __syncthreads();
    }
    float tot = fmaxf(red[0], 1e-12f);
    for (int i = threadIdx.x; i < KCODES; i += 256) r[i] = r[i] / tot;
}

extern "C" void kernel_launch(void* const* d_in, const int* in_sizes, int n_in,
                              void* d_out, int out_size) {
    const float* feat = (const float*)d_in[0];   // [32,256,16,16]
    const float* emb  = (const float*)d_in[1];   // [8192,256]
    float* out = (float*)d_out;

    cudaFuncSetAttribute(k_mma, cudaFuncAttributeMaxDynamicSharedMemorySize, DSMEM);

    k_prep_emb<<<KCODES / 8, 256>>>(emb);                        // 1
    k_prep_f<<<dim3(COLS / 32, CC / 32), dim3(32, 32)>>>(feat);  // 2 (+fsq partials)
    k_fsqm<<<(COLS + 255) / 256, 256>>>();                       // 3
    k_mma<<<dim3(COLS / NTT, KCODES / MT), 256, DSMEM>>>(out);   // 4 (profiled slot)
    k_merge<<<(COLS + 255) / 256, 256>>>();                      // 5
    k_phase2<<<dim3(KCODES / 256, BB), 256>>>(out);              // 6
    k_norm<<<BB, 256>>>(out);                                    // 7
}